// round 2
// baseline (speedup 1.0000x reference)
#include <cuda_runtime.h>

// MulticlassNeighborLayer: out[b,i,c] = 1.7159*tanh( (2/3) * (x[b,i-1]*W[i,c,0]
//                     + x[b,i]*W[i,c,1] + x[b,i+1]*W[i,c,2] + bias[i,c]) )
// B=64, N=16384 (power of 2, circular roll), C=64.
// Store-bound: 268MB out write. Strategy: per-thread register-resident weights
// (loaded once, 64x batch reuse), smem x halo tile, float4 coalesced stores,
// HW tanh.approx.f32.

#define N_CELLS 16384
#define N_MASK  (N_CELLS - 1)
#define NUM_CLASSES 64
#define BATCH 64
#define ITILE 16
#define THREADS 256

__device__ __forceinline__ float tanh_fast(float v) {
    float y;
    asm("tanh.approx.f32 %0, %1;" : "=f"(y) : "f"(v));
    return y;
}

__global__ __launch_bounds__(THREADS)
void mcnl_kernel(const float* __restrict__ x,
                 const float* __restrict__ w,
                 const float* __restrict__ bias,
                 float* __restrict__ out)
{
    __shared__ float sx[BATCH][ITILE + 2];

    const int tid = threadIdx.x;
    const int it  = tid >> 4;          // 0..15 : cell within tile
    const int c0  = (tid & 15) * 4;    // 0,4,...,60 : first class of this thread's 4
    const int i0  = blockIdx.x * ITILE;
    const int i   = i0 + it;

    // Cooperative load of x halo tile: sx[b][k] = x[b, (i0-1+k) mod N]
    // BATCH*(ITILE+2) = 1152 elems over 256 threads: 4-5 per thread.
    for (int j = tid; j < BATCH * (ITILE + 2); j += THREADS) {
        int b = j / (ITILE + 2);
        int k = j - b * (ITILE + 2);
        int gi = (i0 - 1 + k) & N_MASK;
        sx[b][k] = x[b * N_CELLS + gi];
    }

    // Per-thread weights (12 floats) + bias (4), pre-scaled by 2/3.
    const float s = 2.0f / 3.0f;
    const float4* wp = reinterpret_cast<const float4*>(
        w + (size_t)i * NUM_CLASSES * 3 + (size_t)c0 * 3);
    float4 wa = wp[0];
    float4 wb = wp[1];
    float4 wc = wp[2];
    float4 bv = *reinterpret_cast<const float4*>(
        bias + (size_t)i * NUM_CLASSES + c0);

    float tmp[12] = {wa.x, wa.y, wa.z, wa.w,
                     wb.x, wb.y, wb.z, wb.w,
                     wc.x, wc.y, wc.z, wc.w};
    float w0[4], w1[4], w2[4], bb[4];
    #pragma unroll
    for (int j = 0; j < 4; j++) {
        w0[j] = tmp[3 * j + 0] * s;   // weight for x[i-1]
        w1[j] = tmp[3 * j + 1] * s;   // weight for x[i]
        w2[j] = tmp[3 * j + 2] * s;   // weight for x[i+1]
    }
    bb[0] = bv.x * s; bb[1] = bv.y * s; bb[2] = bv.z * s; bb[3] = bv.w * s;

    __syncthreads();

    float* outp = out + (size_t)i * NUM_CLASSES + c0;
    const size_t bstride = (size_t)N_CELLS * NUM_CLASSES;

    #pragma unroll 4
    for (int b = 0; b < BATCH; b++) {
        float l   = sx[b][it];
        float cen = sx[b][it + 1];
        float r   = sx[b][it + 2];

        float o[4];
        #pragma unroll
        for (int j = 0; j < 4; j++) {
            float acc = fmaf(l, w0[j], fmaf(cen, w1[j], fmaf(r, w2[j], bb[j])));
            o[j] = 1.7159f * tanh_fast(acc);
        }
        float4 v = make_float4(o[0], o[1], o[2], o[3]);
        *reinterpret_cast<float4*>(outp + (size_t)b * bstride) = v;
    }
}

extern "C" void kernel_launch(void* const* d_in, const int* in_sizes, int n_in,
                              void* d_out, int out_size) {
    const float* x    = (const float*)d_in[0];
    const float* w    = (const float*)d_in[1];
    const float* bias = (const float*)d_in[2];
    float* out = (float*)d_out;

    dim3 grid(N_CELLS / ITILE);   // 1024 CTAs
    dim3 block(THREADS);
    mcnl_kernel<<<grid, block>>>(x, w, bias, out);
}

// round 3
// speedup vs baseline: 1.1120x; 1.1120x over previous
#include <cuda_runtime.h>

// MulticlassNeighborLayer: out[b,i,c] = 1.7159*tanh( (2/3) * (x[b,i-1]*W[i,c,0]
//                     + x[b,i]*W[i,c,1] + x[b,i+1]*W[i,c,2] + bias[i,c]) )
// B=64, N=16384 (circular), C=64. Store-bound: 268MB output.
// R3: streaming stores (st.global.cs) so the output doesn't thrash L2
// (output is 2x L2 capacity; evict-first drains to DRAM at full rate),
// plus unroll-8 batch loop for more independent STG/MUFU in flight.

#define N_CELLS 16384
#define N_MASK  (N_CELLS - 1)
#define NUM_CLASSES 64
#define BATCH 64
#define ITILE 16
#define THREADS 256

__device__ __forceinline__ float tanh_fast(float v) {
    float y;
    asm("tanh.approx.f32 %0, %1;" : "=f"(y) : "f"(v));
    return y;
}

__device__ __forceinline__ void st_cs_f4(float* p, float4 v) {
    asm volatile("st.global.cs.v4.f32 [%0], {%1,%2,%3,%4};"
                 :: "l"(p), "f"(v.x), "f"(v.y), "f"(v.z), "f"(v.w)
                 : "memory");
}

__global__ __launch_bounds__(THREADS)
void mcnl_kernel(const float* __restrict__ x,
                 const float* __restrict__ w,
                 const float* __restrict__ bias,
                 float* __restrict__ out)
{
    __shared__ float sx[BATCH][ITILE + 2];

    const int tid = threadIdx.x;
    const int it  = tid >> 4;          // 0..15 : cell within tile
    const int c0  = (tid & 15) * 4;    // first class of this thread's 4
    const int i0  = blockIdx.x * ITILE;
    const int i   = i0 + it;

    // Cooperative x halo tile: sx[b][k] = x[b, (i0-1+k) mod N]
    for (int j = tid; j < BATCH * (ITILE + 2); j += THREADS) {
        int b = j / (ITILE + 2);
        int k = j - b * (ITILE + 2);
        int gi = (i0 - 1 + k) & N_MASK;
        sx[b][k] = x[b * N_CELLS + gi];
    }

    // Per-thread weights (12) + bias (4), pre-scaled by 2/3.
    const float s = 2.0f / 3.0f;
    const float4* wp = reinterpret_cast<const float4*>(
        w + (size_t)i * NUM_CLASSES * 3 + (size_t)c0 * 3);
    float4 wa = wp[0];
    float4 wb = wp[1];
    float4 wc = wp[2];
    float4 bv = *reinterpret_cast<const float4*>(
        bias + (size_t)i * NUM_CLASSES + c0);

    float tmp[12] = {wa.x, wa.y, wa.z, wa.w,
                     wb.x, wb.y, wb.z, wb.w,
                     wc.x, wc.y, wc.z, wc.w};
    float w0[4], w1[4], w2[4], bb[4];
    #pragma unroll
    for (int j = 0; j < 4; j++) {
        w0[j] = tmp[3 * j + 0] * s;
        w1[j] = tmp[3 * j + 1] * s;
        w2[j] = tmp[3 * j + 2] * s;
    }
    bb[0] = bv.x * s; bb[1] = bv.y * s; bb[2] = bv.z * s; bb[3] = bv.w * s;

    __syncthreads();

    float* outp = out + (size_t)i * NUM_CLASSES + c0;
    const size_t bstride = (size_t)N_CELLS * NUM_CLASSES;

    #pragma unroll 8
    for (int b = 0; b < BATCH; b++) {
        float l   = sx[b][it];
        float cen = sx[b][it + 1];
        float r   = sx[b][it + 2];

        float o[4];
        #pragma unroll
        for (int j = 0; j < 4; j++) {
            float acc = fmaf(l, w0[j], fmaf(cen, w1[j], fmaf(r, w2[j], bb[j])));
            o[j] = 1.7159f * tanh_fast(acc);
        }
        st_cs_f4(outp + (size_t)b * bstride, make_float4(o[0], o[1], o[2], o[3]));
    }
}

extern "C" void kernel_launch(void* const* d_in, const int* in_sizes, int n_in,
                              void* d_out, int out_size) {
    const float* x    = (const float*)d_in[0];
    const float* w    = (const float*)d_in[1];
    const float* bias = (const float*)d_in[2];
    float* out = (float*)d_out;

    dim3 grid(N_CELLS / ITILE);   // 1024 CTAs (single wave at 8 CTA/SM)
    dim3 block(THREADS);
    mcnl_kernel<<<grid, block>>>(x, w, bias, out);
}